// round 15
// baseline (speedup 1.0000x reference)
#include <cuda_runtime.h>
#include <cuda_bf16.h>
#include <math.h>
#include <stdint.h>

// Problem constants
#define NB   256
#define NS   1024
#define NROWS (NB * NS)   // 262144
#define NCHUNK 16
#define CSTEP  64         // steps per chunk

// Scratch (device globals; padded for branch-free depth-4 prefetch)
__device__ float g_u[(size_t)NROWS * 128 + 512];
__device__ float g_bx[(size_t)NROWS * 8 + 32];
__device__ float g_state[NB * 5];
// bf16 weight images, transposed to [n][k], row stride 136 elements
__device__ __nv_bfloat16 g_B1h[17408], g_B1l[17408], g_B2h[17408];

// ---------------- math helpers ----------------
__device__ __forceinline__ float gelu_exact(float x) {
    return 0.5f * x * (1.0f + erff(x * 0.7071067811865475f));
}
__device__ __forceinline__ float sigmoidf_(float v) { return 1.0f / (1.0f + expf(-v)); }
__device__ __forceinline__ float tanh_fast(float x) {
    float y; asm("tanh.approx.f32 %0, %1;" : "=f"(y) : "f"(x)); return y;
}
__device__ __forceinline__ float gelu_fast(float x) {
    float x2 = x * x;
    float inner = 0.7978845608f * x * fmaf(0.044715f, x2, 1.0f);
    float t = tanh_fast(inner);
    float hx = 0.5f * x;
    return fmaf(hx, t, hx);
}
__device__ __forceinline__ unsigned pack_b2(__nv_bfloat16 a, __nv_bfloat16 b) {
    __nv_bfloat162 t = __halves2bfloat162(a, b);
    return *reinterpret_cast<unsigned*>(&t);
}
__device__ __forceinline__ void split2(float a, float b, unsigned& hi, unsigned& lo) {
    __nv_bfloat16 ha = __float2bfloat16(a), hb = __float2bfloat16(b);
    __nv_bfloat16 la = __float2bfloat16(a - __bfloat162float(ha));
    __nv_bfloat16 lb = __float2bfloat16(b - __bfloat162float(hb));
    hi = pack_b2(ha, hb); lo = pack_b2(la, lb);
}

#define MMA16816(c, a0, a1, a2, a3, b0, b1) \
    asm volatile("mma.sync.aligned.m16n8k16.row.col.f32.bf16.bf16.f32 " \
        "{%0,%1,%2,%3}, {%4,%5,%6,%7}, {%8,%9}, {%0,%1,%2,%3};" \
        : "+f"((c)[0]), "+f"((c)[1]), "+f"((c)[2]), "+f"((c)[3]) \
        : "r"(a0), "r"(a1), "r"(a2), "r"(a3), "r"(b0), "r"(b1))

// ============================================================================
// prep_w: W1 (k,n) -> bf16 hi/lo images; Wc1[5:,:] -> bf16 hi image.
// ============================================================================
__global__ void prep_w(const float* __restrict__ W1, const float* __restrict__ Wc1) {
    int idx = blockIdx.x * 256 + threadIdx.x;
    for (int i = idx; i < 32768; i += 4096) {
        int mat = i >> 14;
        int k = (i >> 7) & 127;
        int n = i & 127;
        float v = mat ? Wc1[(5 + k) * 128 + n] : W1[k * 128 + n];
        __nv_bfloat16 hv = __float2bfloat16(v);
        int o = n * 136 + k;
        if (mat) {
            g_B2h[o] = hv;
        } else {
            g_B1h[o] = hv;
            g_B1l[o] = __float2bfloat16(v - __bfloat162float(hv));
        }
    }
}

// ============================================================================
// p1_mma chunk kernel (unchanged from R14). 128 CTAs per chunk; one CTA =
// two batches' 64-step segments: row r -> batch (2*blk + (r>>6)),
// step ck*64 + (r&63).
// ============================================================================
#define OFF_AH   0
#define OFF_AL   34816
#define OFF_B1H  69632
#define OFF_B1L  104448
#define OFF_B2H  139264
#define OFF_PAR  174080
#define OFF_SB1  (OFF_PAR + 0)
#define OFF_LNG  (OFF_PAR + 512)
#define OFF_LNB  (OFF_PAR + 1024)
#define OFF_BC1  (OFF_PAR + 1536)
#define OFF_WINN (OFF_PAR + 2048)   // 2560 B
#define SMEM_P1  (OFF_PAR + 4608)   // 178688 B

__global__ void __launch_bounds__(256, 1)
p1_mma(const float* __restrict__ x,    const float* __restrict__ b1,
       const float* __restrict__ ln_g, const float* __restrict__ ln_b,
       const float* __restrict__ Winn, const float* __restrict__ binn,
       const float* __restrict__ bc1,  int ck)
{
    extern __shared__ char sm[];
    const int tid = threadIdx.x;
    const int wid = tid >> 5, lane = tid & 31;
    const int g = lane >> 2, q = lane & 3;
    const int b0 = blockIdx.x * 2;
    const int t0c = ck * CSTEP;
    const size_t base0 = (size_t)b0 * NS + t0c;          // rows 0..63
    const size_t base1 = (size_t)(b0 + 1) * NS + t0c;    // rows 64..127

    uint16_t* pAh = (uint16_t*)(sm + OFF_AH);
    uint16_t* pAl = (uint16_t*)(sm + OFF_AL);
    const uint16_t* pB1h = (const uint16_t*)(sm + OFF_B1H);
    const uint16_t* pB1l = (const uint16_t*)(sm + OFF_B1L);
    const uint16_t* pB2h = (const uint16_t*)(sm + OFF_B2H);

    if (tid < 128) {
        ((float*)(sm + OFF_SB1))[tid] = b1[tid];
        ((float*)(sm + OFF_LNG))[tid] = ln_g[tid];
        ((float*)(sm + OFF_LNB))[tid] = ln_b[tid];
        ((float*)(sm + OFF_BC1))[tid] = bc1[tid];
    }
    for (int i = tid; i < 640; i += 256) ((float*)(sm + OFF_WINN))[i] = Winn[i];
    {
        const uint4* s1h = (const uint4*)g_B1h; const uint4* s1l = (const uint4*)g_B1l;
        const uint4* s2h = (const uint4*)g_B2h;
        uint4* d1h = (uint4*)pB1h; uint4* d1l = (uint4*)pB1l;
        uint4* d2h = (uint4*)pB2h;
        for (int i = tid; i < 2176; i += 256) {
            d1h[i] = s1h[i]; d1l[i] = s1l[i]; d2h[i] = s2h[i];
        }
    }
    {
        const float4* xt = (const float4*)x;
        for (int i = tid; i < 4096; i += 256) {
            int row = i >> 5, c4 = i & 31;
            size_t grow = (row < 64 ? base0 : base1) + (row & 63);
            float4 v = xt[grow * 32 + c4];
            int k4 = c4 * 4;
            unsigned h0, l0, h1, l1;
            split2(v.x, v.y, h0, l0);
            split2(v.z, v.w, h1, l1);
            *(uint2*)&pAh[row * 136 + k4] = make_uint2(h0, h1);
            *(uint2*)&pAl[row * 136 + k4] = make_uint2(l0, l1);
        }
    }
    __syncthreads();

    const int rA = wid * 16 + g;
    const int rB = rA + 8;
    const size_t growA = (rA < 64 ? base0 : base1) + (rA & 63);
    const size_t growB = (rB < 64 ? base0 : base1) + (rB & 63);

    // ---- GEMM1: acc = x @ W1 (3-term bf16 split) ----
    float acc[16][4];
#pragma unroll
    for (int nc = 0; nc < 16; nc++)
#pragma unroll
        for (int j = 0; j < 4; j++) acc[nc][j] = 0.f;

#pragma unroll 2
    for (int kc = 0; kc < 8; kc++) {
        const int k0 = kc * 16;
        unsigned ah0 = *(const unsigned*)&pAh[rA * 136 + k0 + 2 * q];
        unsigned ah1 = *(const unsigned*)&pAh[rB * 136 + k0 + 2 * q];
        unsigned ah2 = *(const unsigned*)&pAh[rA * 136 + k0 + 8 + 2 * q];
        unsigned ah3 = *(const unsigned*)&pAh[rB * 136 + k0 + 8 + 2 * q];
        unsigned al0 = *(const unsigned*)&pAl[rA * 136 + k0 + 2 * q];
        unsigned al1 = *(const unsigned*)&pAl[rB * 136 + k0 + 2 * q];
        unsigned al2 = *(const unsigned*)&pAl[rA * 136 + k0 + 8 + 2 * q];
        unsigned al3 = *(const unsigned*)&pAl[rB * 136 + k0 + 8 + 2 * q];
#pragma unroll
        for (int nc = 0; nc < 16; nc++) {
            const int nb = (nc * 8 + g) * 136 + k0 + 2 * q;
            unsigned bh0 = *(const unsigned*)&pB1h[nb];
            unsigned bh1 = *(const unsigned*)&pB1h[nb + 8];
            unsigned bl0 = *(const unsigned*)&pB1l[nb];
            unsigned bl1 = *(const unsigned*)&pB1l[nb + 8];
            MMA16816(acc[nc], ah0, ah1, ah2, ah3, bh0, bh1);
            MMA16816(acc[nc], ah0, ah1, ah2, ah3, bl0, bl1);
            MMA16816(acc[nc], al0, al1, al2, al3, bh0, bh1);
        }
    }

    // ---- Epilogue A ----
    const float* sB1 = (const float*)(sm + OFF_SB1);
    const float* sLG = (const float*)(sm + OFF_LNG);
    const float* sLB = (const float*)(sm + OFF_LNB);
    const float* sWn = (const float*)(sm + OFF_WINN);

    float sumA = 0.f, sqA = 0.f, sumB = 0.f, sqB = 0.f;
#pragma unroll
    for (int nc = 0; nc < 16; nc++) {
        const int c0 = nc * 8 + 2 * q;
        float v0 = acc[nc][0] + sB1[c0], v1 = acc[nc][1] + sB1[c0 + 1];
        float v2 = acc[nc][2] + sB1[c0], v3 = acc[nc][3] + sB1[c0 + 1];
        acc[nc][0] = v0; acc[nc][1] = v1; acc[nc][2] = v2; acc[nc][3] = v3;
        sumA += v0 + v1; sqA = fmaf(v0, v0, fmaf(v1, v1, sqA));
        sumB += v2 + v3; sqB = fmaf(v2, v2, fmaf(v3, v3, sqB));
    }
#pragma unroll
    for (int off = 1; off <= 2; off <<= 1) {
        sumA += __shfl_xor_sync(0xffffffffu, sumA, off);
        sqA  += __shfl_xor_sync(0xffffffffu, sqA,  off);
        sumB += __shfl_xor_sync(0xffffffffu, sumB, off);
        sqB  += __shfl_xor_sync(0xffffffffu, sqB,  off);
    }
    const float muA = sumA * 0.0078125f;
    const float rsA = rsqrtf(sqA * 0.0078125f - muA * muA + 1e-5f);
    const float muB = sumB * 0.0078125f;
    const float rsB = rsqrtf(sqB * 0.0078125f - muB * muB + 1e-5f);

    float bxA[5] = {0, 0, 0, 0, 0}, bxB[5] = {0, 0, 0, 0, 0};
#pragma unroll
    for (int nc = 0; nc < 16; nc++) {
        const int c0 = nc * 8 + 2 * q;
        float h0 = gelu_exact((acc[nc][0] - muA) * rsA * sLG[c0]     + sLB[c0]);
        float h1 = gelu_exact((acc[nc][1] - muA) * rsA * sLG[c0 + 1] + sLB[c0 + 1]);
        float h2 = gelu_exact((acc[nc][2] - muB) * rsB * sLG[c0]     + sLB[c0]);
        float h3 = gelu_exact((acc[nc][3] - muB) * rsB * sLG[c0 + 1] + sLB[c0 + 1]);
        acc[nc][0] = h0; acc[nc][1] = h1; acc[nc][2] = h2; acc[nc][3] = h3;
#pragma unroll
        for (int j = 0; j < 5; j++) {
            bxA[j] = fmaf(h0, sWn[c0 * 5 + j], fmaf(h1, sWn[(c0 + 1) * 5 + j], bxA[j]));
            bxB[j] = fmaf(h2, sWn[c0 * 5 + j], fmaf(h3, sWn[(c0 + 1) * 5 + j], bxB[j]));
        }
    }
#pragma unroll
    for (int off = 1; off <= 2; off <<= 1)
#pragma unroll
        for (int j = 0; j < 5; j++) {
            bxA[j] += __shfl_xor_sync(0xffffffffu, bxA[j], off);
            bxB[j] += __shfl_xor_sync(0xffffffffu, bxB[j], off);
        }
    if (q == 0) {
#pragma unroll
        for (int j = 0; j < 5; j++) {
            float bn = __ldg(&binn[j]);
            g_bx[growA * 8 + j] = bxA[j] + bn;
            g_bx[growB * 8 + j] = bxB[j] + bn;
        }
    }

    // repack h into GEMM2 A-fragments (hi only — corr_scale-damped path)
    unsigned fh[8][4];
#pragma unroll
    for (int kc = 0; kc < 8; kc++) {
        fh[kc][0] = pack_b2(__float2bfloat16(acc[2*kc][0]),     __float2bfloat16(acc[2*kc][1]));
        fh[kc][1] = pack_b2(__float2bfloat16(acc[2*kc][2]),     __float2bfloat16(acc[2*kc][3]));
        fh[kc][2] = pack_b2(__float2bfloat16(acc[2*kc + 1][0]), __float2bfloat16(acc[2*kc + 1][1]));
        fh[kc][3] = pack_b2(__float2bfloat16(acc[2*kc + 1][2]), __float2bfloat16(acc[2*kc + 1][3]));
    }

    // ---- GEMM2: acc = h @ Wc1[5:,:]  (single-term bf16) ----
#pragma unroll
    for (int nc = 0; nc < 16; nc++)
#pragma unroll
        for (int j = 0; j < 4; j++) acc[nc][j] = 0.f;

#pragma unroll 2
    for (int kc = 0; kc < 8; kc++) {
        const int k0 = kc * 16;
#pragma unroll
        for (int nc = 0; nc < 16; nc++) {
            const int nb = (nc * 8 + g) * 136 + k0 + 2 * q;
            unsigned bh0 = *(const unsigned*)&pB2h[nb];
            unsigned bh1 = *(const unsigned*)&pB2h[nb + 8];
            MMA16816(acc[nc], fh[kc][0], fh[kc][1], fh[kc][2], fh[kc][3], bh0, bh1);
        }
    }

    // ---- Epilogue B: +bc1 -> g_u ----
    const float* sBC = (const float*)(sm + OFF_BC1);
    const size_t gra = growA * 128;
    const size_t grb = growB * 128;
#pragma unroll
    for (int nc = 0; nc < 16; nc++) {
        const int c0 = nc * 8 + 2 * q;
        float bA = sBC[c0], bB = sBC[c0 + 1];
        *(float2*)&g_u[gra + c0] = make_float2(acc[nc][0] + bA, acc[nc][1] + bB);
        *(float2*)&g_u[grb + c0] = make_float2(acc[nc][2] + bA, acc[nc][3] + bB);
    }
}

// ============================================================================
// p2 chunk kernel (unchanged from R14). 128 blocks x 64 threads.
// ============================================================================
__global__ void __launch_bounds__(64)
p2_chunk(const float* __restrict__ Wc1, const float* __restrict__ Wc2,
         const float* __restrict__ bc2, const float* __restrict__ corr_scale,
         const float* __restrict__ raw_aL, const float* __restrict__ raw_aT,
         const float* __restrict__ raw_g,  const float* __restrict__ raw_aR,
         const float* __restrict__ omega,  float* __restrict__ out, int ck)
{
    const int warp = threadIdx.x >> 5, lane = threadIdx.x & 31;
    const int b = blockIdx.x * 2 + warp;

    const float aL = sigmoidf_(raw_aL[0]) * 0.15f + 0.85f;
    const float aT = sigmoidf_(raw_aT[0]) * 0.25f + 0.70f;
    const float gg = sigmoidf_(raw_g[0])  * 0.20f + 0.80f;
    const float aR = sigmoidf_(raw_aR[0]) * 0.40f;
    const float om = omega[0];
    const float gc = gg * cosf(om), gs = gg * sinf(om), ngs = -gs;
    const float cs = corr_scale[0];

    const int c0 = lane * 4;
    float Ws[5][4], Wo[4][5], bb[5];
#pragma unroll
    for (int i = 0; i < 5; i++)
#pragma unroll
        for (int c = 0; c < 4; c++) Ws[i][c] = Wc1[i*128 + c0 + c];
#pragma unroll
    for (int c = 0; c < 4; c++)
#pragma unroll
        for (int k = 0; k < 5; k++) Wo[c][k] = Wc2[(c0 + c)*5 + k];
#pragma unroll
    for (int k = 0; k < 5; k++) bb[k] = bc2[k];

    float s0, s1, s2, s3, s4;
    if (ck == 0) {
        s0 = s1 = s2 = s3 = s4 = 0.f;
    } else {
        s0 = g_state[b*5+0]; s1 = g_state[b*5+1]; s2 = g_state[b*5+2];
        s3 = g_state[b*5+3]; s4 = g_state[b*5+4];
    }

    const float4* up  = (const float4*)(g_u + (size_t)b * NS * 128);
    const float*  bxp = g_bx + (size_t)b * NS * 8;
    const int tbase = ck * CSTEP;

    float4 ub[4], xb[4]; float x4b[4];
#pragma unroll
    for (int j = 0; j < 4; j++) {
        ub[j]  = up[(tbase + j) * 32 + lane];
        xb[j]  = *(const float4*)(bxp + (tbase + j) * 8);
        x4b[j] = bxp[(tbase + j) * 8 + 4];
    }

    for (int t0 = tbase; t0 < tbase + CSTEP; t0 += 4) {
#pragma unroll
        for (int j = 0; j < 4; j++) {
            const int t = t0 + j;
            const float4 u = ub[j];
            const float4 x = xb[j];
            const float  x4 = x4b[j];
            ub[j]  = up[(t + 4) * 32 + lane];
            xb[j]  = *(const float4*)(bxp + (t + 4) * 8);
            x4b[j] = bxp[(t + 4) * 8 + 4];

            float l0 = fmaf(s0, aL, x.x);
            float l1 = fmaf(s1, aT, x.y);
            float l2 = fmaf(s2, gc, fmaf(s3, gs,  x.z));
            float l3 = fmaf(s3, gc, fmaf(s2, ngs, x.w));
            float l4 = fmaf(s4, aR, x4);

            float a0 = u.x, a1 = u.y, a2 = u.z, a3 = u.w;
            a0 = fmaf(l0, Ws[0][0], a0); a1 = fmaf(l0, Ws[0][1], a1);
            a2 = fmaf(l0, Ws[0][2], a2); a3 = fmaf(l0, Ws[0][3], a3);
            a0 = fmaf(l1, Ws[1][0], a0); a1 = fmaf(l1, Ws[1][1], a1);
            a2 = fmaf(l1, Ws[1][2], a2); a3 = fmaf(l1, Ws[1][3], a3);
            a0 = fmaf(l2, Ws[2][0], a0); a1 = fmaf(l2, Ws[2][1], a1);
            a2 = fmaf(l2, Ws[2][2], a2); a3 = fmaf(l2, Ws[2][3], a3);
            a0 = fmaf(l3, Ws[3][0], a0); a1 = fmaf(l3, Ws[3][1], a1);
            a2 = fmaf(l3, Ws[3][2], a2); a3 = fmaf(l3, Ws[3][3], a3);
            a0 = fmaf(l4, Ws[4][0], a0); a1 = fmaf(l4, Ws[4][1], a1);
            a2 = fmaf(l4, Ws[4][2], a2); a3 = fmaf(l4, Ws[4][3], a3);

            float m0 = gelu_fast(a0);
            float m1 = gelu_fast(a1);
            float m2 = gelu_fast(a2);
            float m3 = gelu_fast(a3);

            float p0 = m0*Wo[0][0], p1 = m0*Wo[0][1], p2 = m0*Wo[0][2],
                  p3 = m0*Wo[0][3], p4 = m0*Wo[0][4];
            p0 = fmaf(m1, Wo[1][0], p0); p1 = fmaf(m1, Wo[1][1], p1);
            p2 = fmaf(m1, Wo[1][2], p2); p3 = fmaf(m1, Wo[1][3], p3);
            p4 = fmaf(m1, Wo[1][4], p4);
            p0 = fmaf(m2, Wo[2][0], p0); p1 = fmaf(m2, Wo[2][1], p1);
            p2 = fmaf(m2, Wo[2][2], p2); p3 = fmaf(m2, Wo[2][3], p3);
            p4 = fmaf(m2, Wo[2][4], p4);
            p0 = fmaf(m3, Wo[3][0], p0); p1 = fmaf(m3, Wo[3][1], p1);
            p2 = fmaf(m3, Wo[3][2], p2); p3 = fmaf(m3, Wo[3][3], p3);
            p4 = fmaf(m3, Wo[3][4], p4);

#pragma unroll
            for (int off = 16; off; off >>= 1) {
                p0 += __shfl_xor_sync(0xffffffffu, p0, off);
                p1 += __shfl_xor_sync(0xffffffffu, p1, off);
                p2 += __shfl_xor_sync(0xffffffffu, p2, off);
                p3 += __shfl_xor_sync(0xffffffffu, p3, off);
                p4 += __shfl_xor_sync(0xffffffffu, p4, off);
            }
            s0 = fmaf(cs, tanh_fast(p0 + bb[0]), l0);
            s1 = fmaf(cs, tanh_fast(p1 + bb[1]), l1);
            s2 = fmaf(cs, tanh_fast(p2 + bb[2]), l2);
            s3 = fmaf(cs, tanh_fast(p3 + bb[3]), l3);
            s4 = fmaf(cs, tanh_fast(p4 + bb[4]), l4);
        }
    }

    if (lane == 0) {
        if (ck == NCHUNK - 1) {
            out[b*5+0] = s0; out[b*5+1] = s1; out[b*5+2] = s2;
            out[b*5+3] = s3; out[b*5+4] = s4;
        } else {
            g_state[b*5+0] = s0; g_state[b*5+1] = s1; g_state[b*5+2] = s2;
            g_state[b*5+3] = s3; g_state[b*5+4] = s4;
        }
    }
}

// ============================================================================
extern "C" void kernel_launch(void* const* d_in, const int* in_sizes, int n_in,
                              void* d_out, int out_size)
{
    (void)in_sizes; (void)n_in; (void)out_size;
    const float* x    = (const float*)d_in[0];
    const float* W1   = (const float*)d_in[1];
    const float* b1   = (const float*)d_in[2];
    const float* ln_g = (const float*)d_in[3];
    const float* ln_b = (const float*)d_in[4];
    const float* Winn = (const float*)d_in[5];
    const float* binn = (const float*)d_in[6];
    const float* Wc1  = (const float*)d_in[7];
    const float* bc1  = (const float*)d_in[8];
    const float* Wc2  = (const float*)d_in[9];
    const float* bc2  = (const float*)d_in[10];
    const float* cscl = (const float*)d_in[11];
    const float* raL  = (const float*)d_in[12];
    const float* raT  = (const float*)d_in[13];
    const float* rg   = (const float*)d_in[14];
    const float* raR  = (const float*)d_in[15];
    const float* om   = (const float*)d_in[16];

    static int init_done = 0;
    static cudaStream_t s_p1b, s_side;
    static cudaEvent_t evRoot, evP1[NCHUNK], evJoinP1, evJoinP2;
    if (!init_done) {
        cudaFuncSetAttribute(p1_mma, cudaFuncAttributeMaxDynamicSharedMemorySize, SMEM_P1);
        cudaStreamCreateWithFlags(&s_p1b, cudaStreamNonBlocking);
        cudaStreamCreateWithFlags(&s_side, cudaStreamNonBlocking);
        cudaEventCreateWithFlags(&evRoot, cudaEventDisableTiming);
        for (int k = 0; k < NCHUNK; k++)
            cudaEventCreateWithFlags(&evP1[k], cudaEventDisableTiming);
        cudaEventCreateWithFlags(&evJoinP1, cudaEventDisableTiming);
        cudaEventCreateWithFlags(&evJoinP2, cudaEventDisableTiming);
        init_done = 1;
    }

    // origin stream: prep, then fork
    prep_w<<<16, 256>>>(W1, Wc1);
    cudaEventRecord(evRoot, 0);
    cudaStreamWaitEvent(s_p1b, evRoot, 0);

    // p1 chunks alternate between origin stream and s_p1b so consecutive
    // chunks can backfill each other's tails / overlap load-vs-MMA phases.
    for (int k = 0; k < NCHUNK; k++) {
        cudaStream_t st = (k & 1) ? s_p1b : (cudaStream_t)0;
        p1_mma<<<NB / 2, 256, SMEM_P1, st>>>(x, b1, ln_g, ln_b, Winn, binn, bc1, k);
        cudaEventRecord(evP1[k], st);
    }

    // side stream: consumer chunks, each gated on its producer chunk
    for (int k = 0; k < NCHUNK; k++) {
        cudaStreamWaitEvent(s_side, evP1[k], 0);
        p2_chunk<<<NB / 2, 64, 0, s_side>>>(Wc1, Wc2, bc2, cscl, raL, raT, rg, raR, om,
                                            (float*)d_out, k);
    }

    // join both side streams back into the origin stream
    cudaEventRecord(evJoinP1, s_p1b);
    cudaStreamWaitEvent(0, evJoinP1, 0);
    cudaEventRecord(evJoinP2, s_side);
    cudaStreamWaitEvent(0, evJoinP2, 0);
}

// round 16
// speedup vs baseline: 1.2481x; 1.2481x over previous
#include <cuda_runtime.h>
#include <cuda_bf16.h>
#include <math.h>
#include <stdint.h>

// Problem constants
#define NB   256
#define NS   1024
#define NROWS (NB * NS)   // 262144
#define NCHUNK 16
#define CSTEP  64         // steps per chunk

// Scratch (device globals; padded for branch-free depth-4 prefetch)
__device__ float g_u[(size_t)NROWS * 128 + 512];
__device__ float g_bx[(size_t)NROWS * 8 + 32];
__device__ float g_state[NB * 5];
// bf16 weight images, transposed to [n][k], row stride 136 elements
__device__ __nv_bfloat16 g_B1h[17408], g_B1l[17408], g_B2h[17408];

// ---------------- math helpers ----------------
__device__ __forceinline__ float gelu_exact(float x) {
    return 0.5f * x * (1.0f + erff(x * 0.7071067811865475f));
}
__device__ __forceinline__ float sigmoidf_(float v) { return 1.0f / (1.0f + expf(-v)); }
__device__ __forceinline__ float tanh_fast(float x) {
    float y; asm("tanh.approx.f32 %0, %1;" : "=f"(y) : "f"(x)); return y;
}
__device__ __forceinline__ float gelu_fast(float x) {
    float x2 = x * x;
    float inner = 0.7978845608f * x * fmaf(0.044715f, x2, 1.0f);
    float t = tanh_fast(inner);
    float hx = 0.5f * x;
    return fmaf(hx, t, hx);
}
__device__ __forceinline__ unsigned pack_b2(__nv_bfloat16 a, __nv_bfloat16 b) {
    __nv_bfloat162 t = __halves2bfloat162(a, b);
    return *reinterpret_cast<unsigned*>(&t);
}
__device__ __forceinline__ void split2(float a, float b, unsigned& hi, unsigned& lo) {
    __nv_bfloat16 ha = __float2bfloat16(a), hb = __float2bfloat16(b);
    __nv_bfloat16 la = __float2bfloat16(a - __bfloat162float(ha));
    __nv_bfloat16 lb = __float2bfloat16(b - __bfloat162float(hb));
    hi = pack_b2(ha, hb); lo = pack_b2(la, lb);
}
// 16B async copy global->shared (LDGSTS)
__device__ __forceinline__ void cp_async16(void* sdst, const void* gsrc) {
    unsigned sa = (unsigned)__cvta_generic_to_shared(sdst);
    asm volatile("cp.async.cg.shared.global [%0], [%1], 16;" :: "r"(sa), "l"(gsrc) : "memory");
}
#define CP_COMMIT() asm volatile("cp.async.commit_group;" ::: "memory")
#define CP_WAIT0()  asm volatile("cp.async.wait_group 0;" ::: "memory")

#define MMA16816(c, a0, a1, a2, a3, b0, b1) \
    asm volatile("mma.sync.aligned.m16n8k16.row.col.f32.bf16.bf16.f32 " \
        "{%0,%1,%2,%3}, {%4,%5,%6,%7}, {%8,%9}, {%0,%1,%2,%3};" \
        : "+f"((c)[0]), "+f"((c)[1]), "+f"((c)[2]), "+f"((c)[3]) \
        : "r"(a0), "r"(a1), "r"(a2), "r"(a3), "r"(b0), "r"(b1))

// ============================================================================
// prep_w: W1 (k,n) -> bf16 hi/lo images; Wc1[5:,:] -> bf16 hi image.
// ============================================================================
__global__ void prep_w(const float* __restrict__ W1, const float* __restrict__ Wc1) {
    int idx = blockIdx.x * 256 + threadIdx.x;
    for (int i = idx; i < 32768; i += 4096) {
        int mat = i >> 14;
        int k = (i >> 7) & 127;
        int n = i & 127;
        float v = mat ? Wc1[(5 + k) * 128 + n] : W1[k * 128 + n];
        __nv_bfloat16 hv = __float2bfloat16(v);
        int o = n * 136 + k;
        if (mat) {
            g_B2h[o] = hv;
        } else {
            g_B1h[o] = hv;
            g_B1l[o] = __float2bfloat16(v - __bfloat162float(hv));
        }
    }
}

// ============================================================================
// p1_mma chunk kernel. 128 CTAs per chunk; one CTA = two batches' 64-step
// segments: row r -> batch (2*blk + (r>>6)), step ck*64 + (r&63).
// R16: weight images copied via cp.async, overlapped with the x split work.
// ============================================================================
#define OFF_AH   0
#define OFF_AL   34816
#define OFF_B1H  69632
#define OFF_B1L  104448
#define OFF_B2H  139264
#define OFF_PAR  174080
#define OFF_SB1  (OFF_PAR + 0)
#define OFF_LNG  (OFF_PAR + 512)
#define OFF_LNB  (OFF_PAR + 1024)
#define OFF_BC1  (OFF_PAR + 1536)
#define OFF_WINN (OFF_PAR + 2048)   // 2560 B
#define SMEM_P1  (OFF_PAR + 4608)   // 178688 B

__global__ void __launch_bounds__(256, 1)
p1_mma(const float* __restrict__ x,    const float* __restrict__ b1,
       const float* __restrict__ ln_g, const float* __restrict__ ln_b,
       const float* __restrict__ Winn, const float* __restrict__ binn,
       const float* __restrict__ bc1,  int ck)
{
    extern __shared__ char sm[];
    const int tid = threadIdx.x;
    const int wid = tid >> 5, lane = tid & 31;
    const int g = lane >> 2, q = lane & 3;
    const int b0 = blockIdx.x * 2;
    const int t0c = ck * CSTEP;
    const size_t base0 = (size_t)b0 * NS + t0c;          // rows 0..63
    const size_t base1 = (size_t)(b0 + 1) * NS + t0c;    // rows 64..127

    uint16_t* pAh = (uint16_t*)(sm + OFF_AH);
    uint16_t* pAl = (uint16_t*)(sm + OFF_AL);
    const uint16_t* pB1h = (const uint16_t*)(sm + OFF_B1H);
    const uint16_t* pB1l = (const uint16_t*)(sm + OFF_B1L);
    const uint16_t* pB2h = (const uint16_t*)(sm + OFF_B2H);

    // ---- async weight-image copies FIRST (latency hidden by x work below) ----
    {
        const uint4* s1h = (const uint4*)g_B1h;
        const uint4* s1l = (const uint4*)g_B1l;
        const uint4* s2h = (const uint4*)g_B2h;
        uint4* d1h = (uint4*)(sm + OFF_B1H);
        uint4* d1l = (uint4*)(sm + OFF_B1L);
        uint4* d2h = (uint4*)(sm + OFF_B2H);
        for (int i = tid; i < 2176; i += 256) {
            cp_async16(&d1h[i], &s1h[i]);
            cp_async16(&d1l[i], &s1l[i]);
            cp_async16(&d2h[i], &s2h[i]);
        }
        CP_COMMIT();
    }

    if (tid < 128) {
        ((float*)(sm + OFF_SB1))[tid] = b1[tid];
        ((float*)(sm + OFF_LNG))[tid] = ln_g[tid];
        ((float*)(sm + OFF_LNB))[tid] = ln_b[tid];
        ((float*)(sm + OFF_BC1))[tid] = bc1[tid];
    }
    for (int i = tid; i < 640; i += 256) ((float*)(sm + OFF_WINN))[i] = Winn[i];

    // x tile: load + bf16 hi/lo split (overlaps the async weight copies)
    {
        const float4* xt = (const float4*)x;
        for (int i = tid; i < 4096; i += 256) {
            int row = i >> 5, c4 = i & 31;
            size_t grow = (row < 64 ? base0 : base1) + (row & 63);
            float4 v = xt[grow * 32 + c4];
            int k4 = c4 * 4;
            unsigned h0, l0, h1, l1;
            split2(v.x, v.y, h0, l0);
            split2(v.z, v.w, h1, l1);
            *(uint2*)&pAh[row * 136 + k4] = make_uint2(h0, h1);
            *(uint2*)&pAl[row * 136 + k4] = make_uint2(l0, l1);
        }
    }
    CP_WAIT0();
    __syncthreads();

    const int rA = wid * 16 + g;
    const int rB = rA + 8;
    const size_t growA = (rA < 64 ? base0 : base1) + (rA & 63);
    const size_t growB = (rB < 64 ? base0 : base1) + (rB & 63);

    // ---- GEMM1: acc = x @ W1 (3-term bf16 split) ----
    float acc[16][4];
#pragma unroll
    for (int nc = 0; nc < 16; nc++)
#pragma unroll
        for (int j = 0; j < 4; j++) acc[nc][j] = 0.f;

#pragma unroll 2
    for (int kc = 0; kc < 8; kc++) {
        const int k0 = kc * 16;
        unsigned ah0 = *(const unsigned*)&pAh[rA * 136 + k0 + 2 * q];
        unsigned ah1 = *(const unsigned*)&pAh[rB * 136 + k0 + 2 * q];
        unsigned ah2 = *(const unsigned*)&pAh[rA * 136 + k0 + 8 + 2 * q];
        unsigned ah3 = *(const unsigned*)&pAh[rB * 136 + k0 + 8 + 2 * q];
        unsigned al0 = *(const unsigned*)&pAl[rA * 136 + k0 + 2 * q];
        unsigned al1 = *(const unsigned*)&pAl[rB * 136 + k0 + 2 * q];
        unsigned al2 = *(const unsigned*)&pAl[rA * 136 + k0 + 8 + 2 * q];
        unsigned al3 = *(const unsigned*)&pAl[rB * 136 + k0 + 8 + 2 * q];
#pragma unroll
        for (int nc = 0; nc < 16; nc++) {
            const int nb = (nc * 8 + g) * 136 + k0 + 2 * q;
            unsigned bh0 = *(const unsigned*)&pB1h[nb];
            unsigned bh1 = *(const unsigned*)&pB1h[nb + 8];
            unsigned bl0 = *(const unsigned*)&pB1l[nb];
            unsigned bl1 = *(const unsigned*)&pB1l[nb + 8];
            MMA16816(acc[nc], ah0, ah1, ah2, ah3, bh0, bh1);
            MMA16816(acc[nc], ah0, ah1, ah2, ah3, bl0, bl1);
            MMA16816(acc[nc], al0, al1, al2, al3, bh0, bh1);
        }
    }

    // ---- Epilogue A ----
    const float* sB1 = (const float*)(sm + OFF_SB1);
    const float* sLG = (const float*)(sm + OFF_LNG);
    const float* sLB = (const float*)(sm + OFF_LNB);
    const float* sWn = (const float*)(sm + OFF_WINN);

    float sumA = 0.f, sqA = 0.f, sumB = 0.f, sqB = 0.f;
#pragma unroll
    for (int nc = 0; nc < 16; nc++) {
        const int c0 = nc * 8 + 2 * q;
        float v0 = acc[nc][0] + sB1[c0], v1 = acc[nc][1] + sB1[c0 + 1];
        float v2 = acc[nc][2] + sB1[c0], v3 = acc[nc][3] + sB1[c0 + 1];
        acc[nc][0] = v0; acc[nc][1] = v1; acc[nc][2] = v2; acc[nc][3] = v3;
        sumA += v0 + v1; sqA = fmaf(v0, v0, fmaf(v1, v1, sqA));
        sumB += v2 + v3; sqB = fmaf(v2, v2, fmaf(v3, v3, sqB));
    }
#pragma unroll
    for (int off = 1; off <= 2; off <<= 1) {
        sumA += __shfl_xor_sync(0xffffffffu, sumA, off);
        sqA  += __shfl_xor_sync(0xffffffffu, sqA,  off);
        sumB += __shfl_xor_sync(0xffffffffu, sumB, off);
        sqB  += __shfl_xor_sync(0xffffffffu, sqB,  off);
    }
    const float muA = sumA * 0.0078125f;
    const float rsA = rsqrtf(sqA * 0.0078125f - muA * muA + 1e-5f);
    const float muB = sumB * 0.0078125f;
    const float rsB = rsqrtf(sqB * 0.0078125f - muB * muB + 1e-5f);

    float bxA[5] = {0, 0, 0, 0, 0}, bxB[5] = {0, 0, 0, 0, 0};
#pragma unroll
    for (int nc = 0; nc < 16; nc++) {
        const int c0 = nc * 8 + 2 * q;
        float h0 = gelu_exact((acc[nc][0] - muA) * rsA * sLG[c0]     + sLB[c0]);
        float h1 = gelu_exact((acc[nc][1] - muA) * rsA * sLG[c0 + 1] + sLB[c0 + 1]);
        float h2 = gelu_exact((acc[nc][2] - muB) * rsB * sLG[c0]     + sLB[c0]);
        float h3 = gelu_exact((acc[nc][3] - muB) * rsB * sLG[c0 + 1] + sLB[c0 + 1]);
        acc[nc][0] = h0; acc[nc][1] = h1; acc[nc][2] = h2; acc[nc][3] = h3;
#pragma unroll
        for (int j = 0; j < 5; j++) {
            bxA[j] = fmaf(h0, sWn[c0 * 5 + j], fmaf(h1, sWn[(c0 + 1) * 5 + j], bxA[j]));
            bxB[j] = fmaf(h2, sWn[c0 * 5 + j], fmaf(h3, sWn[(c0 + 1) * 5 + j], bxB[j]));
        }
    }
#pragma unroll
    for (int off = 1; off <= 2; off <<= 1)
#pragma unroll
        for (int j = 0; j < 5; j++) {
            bxA[j] += __shfl_xor_sync(0xffffffffu, bxA[j], off);
            bxB[j] += __shfl_xor_sync(0xffffffffu, bxB[j], off);
        }
    if (q == 0) {
#pragma unroll
        for (int j = 0; j < 5; j++) {
            float bn = __ldg(&binn[j]);
            g_bx[growA * 8 + j] = bxA[j] + bn;
            g_bx[growB * 8 + j] = bxB[j] + bn;
        }
    }

    // repack h into GEMM2 A-fragments (hi only — corr_scale-damped path)
    unsigned fh[8][4];
#pragma unroll
    for (int kc = 0; kc < 8; kc++) {
        fh[kc][0] = pack_b2(__float2bfloat16(acc[2*kc][0]),     __float2bfloat16(acc[2*kc][1]));
        fh[kc][1] = pack_b2(__float2bfloat16(acc[2*kc][2]),     __float2bfloat16(acc[2*kc][3]));
        fh[kc][2] = pack_b2(__float2bfloat16(acc[2*kc + 1][0]), __float2bfloat16(acc[2*kc + 1][1]));
        fh[kc][3] = pack_b2(__float2bfloat16(acc[2*kc + 1][2]), __float2bfloat16(acc[2*kc + 1][3]));
    }

    // ---- GEMM2: acc = h @ Wc1[5:,:]  (single-term bf16) ----
#pragma unroll
    for (int nc = 0; nc < 16; nc++)
#pragma unroll
        for (int j = 0; j < 4; j++) acc[nc][j] = 0.f;

#pragma unroll 2
    for (int kc = 0; kc < 8; kc++) {
        const int k0 = kc * 16;
#pragma unroll
        for (int nc = 0; nc < 16; nc++) {
            const int nb = (nc * 8 + g) * 136 + k0 + 2 * q;
            unsigned bh0 = *(const unsigned*)&pB2h[nb];
            unsigned bh1 = *(const unsigned*)&pB2h[nb + 8];
            MMA16816(acc[nc], fh[kc][0], fh[kc][1], fh[kc][2], fh[kc][3], bh0, bh1);
        }
    }

    // ---- Epilogue B: +bc1 -> g_u ----
    const float* sBC = (const float*)(sm + OFF_BC1);
    const size_t gra = growA * 128;
    const size_t grb = growB * 128;
#pragma unroll
    for (int nc = 0; nc < 16; nc++) {
        const int c0 = nc * 8 + 2 * q;
        float bA = sBC[c0], bB = sBC[c0 + 1];
        *(float2*)&g_u[gra + c0] = make_float2(acc[nc][0] + bA, acc[nc][1] + bB);
        *(float2*)&g_u[grb + c0] = make_float2(acc[nc][2] + bA, acc[nc][3] + bB);
    }
}

// ============================================================================
// p2 chunk kernel (unchanged). 128 blocks x 64 threads.
// ============================================================================
__global__ void __launch_bounds__(64)
p2_chunk(const float* __restrict__ Wc1, const float* __restrict__ Wc2,
         const float* __restrict__ bc2, const float* __restrict__ corr_scale,
         const float* __restrict__ raw_aL, const float* __restrict__ raw_aT,
         const float* __restrict__ raw_g,  const float* __restrict__ raw_aR,
         const float* __restrict__ omega,  float* __restrict__ out, int ck)
{
    const int warp = threadIdx.x >> 5, lane = threadIdx.x & 31;
    const int b = blockIdx.x * 2 + warp;

    const float aL = sigmoidf_(raw_aL[0]) * 0.15f + 0.85f;
    const float aT = sigmoidf_(raw_aT[0]) * 0.25f + 0.70f;
    const float gg = sigmoidf_(raw_g[0])  * 0.20f + 0.80f;
    const float aR = sigmoidf_(raw_aR[0]) * 0.40f;
    const float om = omega[0];
    const float gc = gg * cosf(om), gs = gg * sinf(om), ngs = -gs;
    const float cs = corr_scale[0];

    const int c0 = lane * 4;
    float Ws[5][4], Wo[4][5], bb[5];
#pragma unroll
    for (int i = 0; i < 5; i++)
#pragma unroll
        for (int c = 0; c < 4; c++) Ws[i][c] = Wc1[i*128 + c0 + c];
#pragma unroll
    for (int c = 0; c < 4; c++)
#pragma unroll
        for (int k = 0; k < 5; k++) Wo[c][k] = Wc2[(c0 + c)*5 + k];
#pragma unroll
    for (int k = 0; k < 5; k++) bb[k] = bc2[k];

    float s0, s1, s2, s3, s4;
    if (ck == 0) {
        s0 = s1 = s2 = s3 = s4 = 0.f;
    } else {
        s0 = g_state[b*5+0]; s1 = g_state[b*5+1]; s2 = g_state[b*5+2];
        s3 = g_state[b*5+3]; s4 = g_state[b*5+4];
    }

    const float4* up  = (const float4*)(g_u + (size_t)b * NS * 128);
    const float*  bxp = g_bx + (size_t)b * NS * 8;
    const int tbase = ck * CSTEP;

    float4 ub[4], xb[4]; float x4b[4];
#pragma unroll
    for (int j = 0; j < 4; j++) {
        ub[j]  = up[(tbase + j) * 32 + lane];
        xb[j]  = *(const float4*)(bxp + (tbase + j) * 8);
        x4b[j] = bxp[(tbase + j) * 8 + 4];
    }

    for (int t0 = tbase; t0 < tbase + CSTEP; t0 += 4) {
#pragma unroll
        for (int j = 0; j < 4; j++) {
            const int t = t0 + j;
            const float4 u = ub[j];
            const float4 x = xb[j];
            const float  x4 = x4b[j];
            ub[j]  = up[(t + 4) * 32 + lane];
            xb[j]  = *(const float4*)(bxp + (t + 4) * 8);
            x4b[j] = bxp[(t + 4) * 8 + 4];

            float l0 = fmaf(s0, aL, x.x);
            float l1 = fmaf(s1, aT, x.y);
            float l2 = fmaf(s2, gc, fmaf(s3, gs,  x.z));
            float l3 = fmaf(s3, gc, fmaf(s2, ngs, x.w));
            float l4 = fmaf(s4, aR, x4);

            float a0 = u.x, a1 = u.y, a2 = u.z, a3 = u.w;
            a0 = fmaf(l0, Ws[0][0], a0); a1 = fmaf(l0, Ws[0][1], a1);
            a2 = fmaf(l0, Ws[0][2], a2); a3 = fmaf(l0, Ws[0][3], a3);
            a0 = fmaf(l1, Ws[1][0], a0); a1 = fmaf(l1, Ws[1][1], a1);
            a2 = fmaf(l1, Ws[1][2], a2); a3 = fmaf(l1, Ws[1][3], a3);
            a0 = fmaf(l2, Ws[2][0], a0); a1 = fmaf(l2, Ws[2][1], a1);
            a2 = fmaf(l2, Ws[2][2], a2); a3 = fmaf(l2, Ws[2][3], a3);
            a0 = fmaf(l3, Ws[3][0], a0); a1 = fmaf(l3, Ws[3][1], a1);
            a2 = fmaf(l3, Ws[3][2], a2); a3 = fmaf(l3, Ws[3][3], a3);
            a0 = fmaf(l4, Ws[4][0], a0); a1 = fmaf(l4, Ws[4][1], a1);
            a2 = fmaf(l4, Ws[4][2], a2); a3 = fmaf(l4, Ws[4][3], a3);

            float m0 = gelu_fast(a0);
            float m1 = gelu_fast(a1);
            float m2 = gelu_fast(a2);
            float m3 = gelu_fast(a3);

            float p0 = m0*Wo[0][0], p1 = m0*Wo[0][1], p2 = m0*Wo[0][2],
                  p3 = m0*Wo[0][3], p4 = m0*Wo[0][4];
            p0 = fmaf(m1, Wo[1][0], p0); p1 = fmaf(m1, Wo[1][1], p1);
            p2 = fmaf(m1, Wo[1][2], p2); p3 = fmaf(m1, Wo[1][3], p3);
            p4 = fmaf(m1, Wo[1][4], p4);
            p0 = fmaf(m2, Wo[2][0], p0); p1 = fmaf(m2, Wo[2][1], p1);
            p2 = fmaf(m2, Wo[2][2], p2); p3 = fmaf(m2, Wo[2][3], p3);
            p4 = fmaf(m2, Wo[2][4], p4);
            p0 = fmaf(m3, Wo[3][0], p0); p1 = fmaf(m3, Wo[3][1], p1);
            p2 = fmaf(m3, Wo[3][2], p2); p3 = fmaf(m3, Wo[3][3], p3);
            p4 = fmaf(m3, Wo[3][4], p4);

#pragma unroll
            for (int off = 16; off; off >>= 1) {
                p0 += __shfl_xor_sync(0xffffffffu, p0, off);
                p1 += __shfl_xor_sync(0xffffffffu, p1, off);
                p2 += __shfl_xor_sync(0xffffffffu, p2, off);
                p3 += __shfl_xor_sync(0xffffffffu, p3, off);
                p4 += __shfl_xor_sync(0xffffffffu, p4, off);
            }
            s0 = fmaf(cs, tanh_fast(p0 + bb[0]), l0);
            s1 = fmaf(cs, tanh_fast(p1 + bb[1]), l1);
            s2 = fmaf(cs, tanh_fast(p2 + bb[2]), l2);
            s3 = fmaf(cs, tanh_fast(p3 + bb[3]), l3);
            s4 = fmaf(cs, tanh_fast(p4 + bb[4]), l4);
        }
    }

    if (lane == 0) {
        if (ck == NCHUNK - 1) {
            out[b*5+0] = s0; out[b*5+1] = s1; out[b*5+2] = s2;
            out[b*5+3] = s3; out[b*5+4] = s4;
        } else {
            g_state[b*5+0] = s0; g_state[b*5+1] = s1; g_state[b*5+2] = s2;
            g_state[b*5+3] = s3; g_state[b*5+4] = s4;
        }
    }
}

// ============================================================================
extern "C" void kernel_launch(void* const* d_in, const int* in_sizes, int n_in,
                              void* d_out, int out_size)
{
    (void)in_sizes; (void)n_in; (void)out_size;
    const float* x    = (const float*)d_in[0];
    const float* W1   = (const float*)d_in[1];
    const float* b1   = (const float*)d_in[2];
    const float* ln_g = (const float*)d_in[3];
    const float* ln_b = (const float*)d_in[4];
    const float* Winn = (const float*)d_in[5];
    const float* binn = (const float*)d_in[6];
    const float* Wc1  = (const float*)d_in[7];
    const float* bc1  = (const float*)d_in[8];
    const float* Wc2  = (const float*)d_in[9];
    const float* bc2  = (const float*)d_in[10];
    const float* cscl = (const float*)d_in[11];
    const float* raL  = (const float*)d_in[12];
    const float* raT  = (const float*)d_in[13];
    const float* rg   = (const float*)d_in[14];
    const float* raR  = (const float*)d_in[15];
    const float* om   = (const float*)d_in[16];

    static int init_done = 0;
    static cudaStream_t s_side;
    static cudaEvent_t evP1[NCHUNK], evJoin;
    if (!init_done) {
        cudaFuncSetAttribute(p1_mma, cudaFuncAttributeMaxDynamicSharedMemorySize, SMEM_P1);
        cudaStreamCreateWithFlags(&s_side, cudaStreamNonBlocking);
        for (int k = 0; k < NCHUNK; k++)
            cudaEventCreateWithFlags(&evP1[k], cudaEventDisableTiming);
        cudaEventCreateWithFlags(&evJoin, cudaEventDisableTiming);
        init_done = 1;
    }

    // main (capture-origin) stream: prep + producer chunks (128 CTAs each)
    prep_w<<<16, 256>>>(W1, Wc1);
    for (int k = 0; k < NCHUNK; k++) {
        p1_mma<<<NB / 2, 256, SMEM_P1>>>(x, b1, ln_g, ln_b, Winn, binn, bc1, k);
        cudaEventRecord(evP1[k], 0);
    }
    // side stream: consumer chunks, each gated on its producer chunk
    for (int k = 0; k < NCHUNK; k++) {
        cudaStreamWaitEvent(s_side, evP1[k], 0);
        p2_chunk<<<NB / 2, 64, 0, s_side>>>(Wc1, Wc2, bc2, cscl, raL, raT, rg, raR, om,
                                            (float*)d_out, k);
    }
    // join side stream back into the origin stream
    cudaEventRecord(evJoin, s_side);
    cudaStreamWaitEvent(0, evJoin, 0);
}

// round 17
// speedup vs baseline: 1.2611x; 1.0104x over previous
#include <cuda_runtime.h>
#include <cuda_bf16.h>
#include <math.h>
#include <stdint.h>

// Problem constants
#define NB   256
#define NS   1024
#define NROWS (NB * NS)   // 262144
#define NCHUNK 8
#define CSTEP  128        // steps per chunk

// Scratch (device globals; padded for branch-free depth-4 prefetch)
__device__ float g_u[(size_t)NROWS * 128 + 512];
__device__ float g_bx[(size_t)NROWS * 8 + 32];
__device__ float g_state[NB * 5];
// bf16 weight images, transposed to [n][k], row stride 136 elements (272 B)
__device__ __nv_bfloat16 g_B1h[17408], g_B1l[17408], g_B2h[17408];

// ---------------- math helpers ----------------
__device__ __forceinline__ float gelu_exact(float x) {
    return 0.5f * x * (1.0f + erff(x * 0.7071067811865475f));
}
__device__ __forceinline__ float sigmoidf_(float v) { return 1.0f / (1.0f + expf(-v)); }
__device__ __forceinline__ float tanh_fast(float x) {
    float y; asm("tanh.approx.f32 %0, %1;" : "=f"(y) : "f"(x)); return y;
}
__device__ __forceinline__ float gelu_fast(float x) {
    float x2 = x * x;
    float inner = 0.7978845608f * x * fmaf(0.044715f, x2, 1.0f);
    float t = tanh_fast(inner);
    float hx = 0.5f * x;
    return fmaf(hx, t, hx);
}
__device__ __forceinline__ unsigned pack_b2(__nv_bfloat16 a, __nv_bfloat16 b) {
    __nv_bfloat162 t = __halves2bfloat162(a, b);
    return *reinterpret_cast<unsigned*>(&t);
}
__device__ __forceinline__ void split2(float a, float b, unsigned& hi, unsigned& lo) {
    __nv_bfloat16 ha = __float2bfloat16(a), hb = __float2bfloat16(b);
    __nv_bfloat16 la = __float2bfloat16(a - __bfloat162float(ha));
    __nv_bfloat16 lb = __float2bfloat16(b - __bfloat162float(hb));
    hi = pack_b2(ha, hb); lo = pack_b2(la, lb);
}
__device__ __forceinline__ void cp_async16(void* sdst, const void* gsrc) {
    unsigned sa = (unsigned)__cvta_generic_to_shared(sdst);
    asm volatile("cp.async.cg.shared.global [%0], [%1], 16;" :: "r"(sa), "l"(gsrc) : "memory");
}
#define CP_COMMIT() asm volatile("cp.async.commit_group;" ::: "memory")
#define CP_WAIT1()  asm volatile("cp.async.wait_group 1;" ::: "memory")

#define MMA16816(c, a0, a1, a2, a3, b0, b1) \
    asm volatile("mma.sync.aligned.m16n8k16.row.col.f32.bf16.bf16.f32 " \
        "{%0,%1,%2,%3}, {%4,%5,%6,%7}, {%8,%9}, {%0,%1,%2,%3};" \
        : "+f"((c)[0]), "+f"((c)[1]), "+f"((c)[2]), "+f"((c)[3]) \
        : "r"(a0), "r"(a1), "r"(a2), "r"(a3), "r"(b0), "r"(b1))

// ============================================================================
// prep_w: W1 (k,n) -> bf16 hi/lo images; Wc1[5:,:] -> bf16 hi image.
// ============================================================================
__global__ void prep_w(const float* __restrict__ W1, const float* __restrict__ Wc1) {
    int idx = blockIdx.x * 256 + threadIdx.x;
    for (int i = idx; i < 32768; i += 4096) {
        int mat = i >> 14;
        int k = (i >> 7) & 127;
        int n = i & 127;
        float v = mat ? Wc1[(5 + k) * 128 + n] : W1[k * 128 + n];
        __nv_bfloat16 hv = __float2bfloat16(v);
        int o = n * 136 + k;
        if (mat) {
            g_B2h[o] = hv;
        } else {
            g_B1h[o] = hv;
            g_B1l[o] = __float2bfloat16(v - __bfloat162float(hv));
        }
    }
}

// ============================================================================
// p1_mma chunk kernel, 2 CTAs/SM. 256 CTAs per chunk; CTA = one batch's
// 128-step segment (rows = step offsets). B weight slices streamed through a
// 3-stage cp.async pipeline (12 KB/stage, 48B rows -> conflict-free LDS).
// SMEM 111 KB, __launch_bounds__(256, 2).
// ============================================================================
#define OFF_AH   0
#define OFF_AL   34816
#define OFF_BST  69632            // 3 stages x 12288 B (h at +0, l at +6144)
#define STG_SZ   12288
#define OFF_PAR  106496
#define OFF_SB1  (OFF_PAR + 0)
#define OFF_LNG  (OFF_PAR + 512)
#define OFF_LNB  (OFF_PAR + 1024)
#define OFF_BC1  (OFF_PAR + 1536)
#define OFF_WINN (OFF_PAR + 2048)   // 2560 B
#define OFF_BINN (OFF_PAR + 4608)   // 32 B
#define SMEM_P1  (OFF_PAR + 4640)   // 111136 B

__device__ __forceinline__ void issue_b1(char* sm, int stage, int kc, int tid) {
    int n = tid >> 1, half = tid & 1;
    int so = kc * 32 + half * 16;            // byte offset within row (k slice)
    char* d = sm + OFF_BST + stage * STG_SZ + n * 48 + half * 16;
    cp_async16(d,        (const char*)g_B1h + n * 272 + so);
    cp_async16(d + 6144, (const char*)g_B1l + n * 272 + so);
}
__device__ __forceinline__ void issue_b2(char* sm, int stage, int kc, int tid) {
    int n = tid >> 1, half = tid & 1;
    cp_async16(sm + OFF_BST + stage * STG_SZ + n * 48 + half * 16,
               (const char*)g_B2h + n * 272 + kc * 32 + half * 16);
}

__global__ void __launch_bounds__(256, 2)
p1_mma(const float* __restrict__ x,    const float* __restrict__ b1,
       const float* __restrict__ ln_g, const float* __restrict__ ln_b,
       const float* __restrict__ Winn, const float* __restrict__ binn,
       const float* __restrict__ bc1,  int ck)
{
    extern __shared__ char sm[];
    const int tid = threadIdx.x;
    const int wid = tid >> 5, lane = tid & 31;
    const int g = lane >> 2, q = lane & 3;
    const size_t base = (size_t)blockIdx.x * NS + ck * CSTEP;  // global row of tile row 0

    uint16_t* pAh = (uint16_t*)(sm + OFF_AH);
    uint16_t* pAl = (uint16_t*)(sm + OFF_AL);

    // prologue: first two B1 slices in flight
    issue_b1(sm, 0, 0, tid); CP_COMMIT();
    issue_b1(sm, 1, 1, tid); CP_COMMIT();

    if (tid < 128) {
        ((float*)(sm + OFF_SB1))[tid] = b1[tid];
        ((float*)(sm + OFF_LNG))[tid] = ln_g[tid];
        ((float*)(sm + OFF_LNB))[tid] = ln_b[tid];
        ((float*)(sm + OFF_BC1))[tid] = bc1[tid];
    }
    for (int i = tid; i < 640; i += 256) ((float*)(sm + OFF_WINN))[i] = Winn[i];
    if (tid < 5) ((float*)(sm + OFF_BINN))[tid] = binn[tid];

    // x tile (contiguous 128 rows) -> bf16 hi/lo split
    {
        const float4* xt = (const float4*)(x + base * 128);
        for (int i = tid; i < 4096; i += 256) {
            float4 v = xt[i];
            int row = i >> 5, k4 = (i & 31) * 4;
            unsigned h0, l0, h1, l1;
            split2(v.x, v.y, h0, l0);
            split2(v.z, v.w, h1, l1);
            *(uint2*)&pAh[row * 136 + k4] = make_uint2(h0, h1);
            *(uint2*)&pAl[row * 136 + k4] = make_uint2(l0, l1);
        }
    }

    const int rA = wid * 16 + g;
    const int rB = rA + 8;

    // ---- GEMM1: acc = x @ W1 (3-term bf16 split), streamed B ----
    float acc[16][4];
#pragma unroll
    for (int nc = 0; nc < 16; nc++)
#pragma unroll
        for (int j = 0; j < 4; j++) acc[nc][j] = 0.f;

    for (int kc = 0; kc < 8; kc++) {
        CP_WAIT1();
        __syncthreads();
        if (kc < 6) issue_b1(sm, (kc + 2) % 3, kc + 2, tid);
        CP_COMMIT();

        const int k0 = kc * 16;
        unsigned ah0 = *(const unsigned*)&pAh[rA * 136 + k0 + 2 * q];
        unsigned ah1 = *(const unsigned*)&pAh[rB * 136 + k0 + 2 * q];
        unsigned ah2 = *(const unsigned*)&pAh[rA * 136 + k0 + 8 + 2 * q];
        unsigned ah3 = *(const unsigned*)&pAh[rB * 136 + k0 + 8 + 2 * q];
        unsigned al0 = *(const unsigned*)&pAl[rA * 136 + k0 + 2 * q];
        unsigned al1 = *(const unsigned*)&pAl[rB * 136 + k0 + 2 * q];
        unsigned al2 = *(const unsigned*)&pAl[rA * 136 + k0 + 8 + 2 * q];
        unsigned al3 = *(const unsigned*)&pAl[rB * 136 + k0 + 8 + 2 * q];

        const char* stg = sm + OFF_BST + (kc % 3) * STG_SZ;
#pragma unroll
        for (int nc = 0; nc < 16; nc++) {
            const char* bp = stg + (nc * 8 + g) * 48 + 4 * q;
            unsigned bh0 = *(const unsigned*)bp;
            unsigned bh1 = *(const unsigned*)(bp + 16);
            unsigned bl0 = *(const unsigned*)(bp + 6144);
            unsigned bl1 = *(const unsigned*)(bp + 6144 + 16);
            MMA16816(acc[nc], ah0, ah1, ah2, ah3, bh0, bh1);
            MMA16816(acc[nc], ah0, ah1, ah2, ah3, bl0, bl1);
            MMA16816(acc[nc], al0, al1, al2, al3, bh0, bh1);
        }
    }

    // prefetch first two B2 slices (hidden behind epilogue A)
    __syncthreads();
    issue_b2(sm, 0, 0, tid); CP_COMMIT();
    issue_b2(sm, 1, 1, tid); CP_COMMIT();

    // ---- Epilogue A ----
    const float* sB1 = (const float*)(sm + OFF_SB1);
    const float* sLG = (const float*)(sm + OFF_LNG);
    const float* sLB = (const float*)(sm + OFF_LNB);
    const float* sWn = (const float*)(sm + OFF_WINN);

    float sumA = 0.f, sqA = 0.f, sumB = 0.f, sqB = 0.f;
#pragma unroll
    for (int nc = 0; nc < 16; nc++) {
        const int c0 = nc * 8 + 2 * q;
        float v0 = acc[nc][0] + sB1[c0], v1 = acc[nc][1] + sB1[c0 + 1];
        float v2 = acc[nc][2] + sB1[c0], v3 = acc[nc][3] + sB1[c0 + 1];
        acc[nc][0] = v0; acc[nc][1] = v1; acc[nc][2] = v2; acc[nc][3] = v3;
        sumA += v0 + v1; sqA = fmaf(v0, v0, fmaf(v1, v1, sqA));
        sumB += v2 + v3; sqB = fmaf(v2, v2, fmaf(v3, v3, sqB));
    }
#pragma unroll
    for (int off = 1; off <= 2; off <<= 1) {
        sumA += __shfl_xor_sync(0xffffffffu, sumA, off);
        sqA  += __shfl_xor_sync(0xffffffffu, sqA,  off);
        sumB += __shfl_xor_sync(0xffffffffu, sumB, off);
        sqB  += __shfl_xor_sync(0xffffffffu, sqB,  off);
    }
    const float muA = sumA * 0.0078125f;
    const float rsA = rsqrtf(sqA * 0.0078125f - muA * muA + 1e-5f);
    const float muB = sumB * 0.0078125f;
    const float rsB = rsqrtf(sqB * 0.0078125f - muB * muB + 1e-5f);

    float bxA[5] = {0, 0, 0, 0, 0}, bxB[5] = {0, 0, 0, 0, 0};
#pragma unroll
    for (int nc = 0; nc < 16; nc++) {
        const int c0 = nc * 8 + 2 * q;
        float h0 = gelu_exact((acc[nc][0] - muA) * rsA * sLG[c0]     + sLB[c0]);
        float h1 = gelu_exact((acc[nc][1] - muA) * rsA * sLG[c0 + 1] + sLB[c0 + 1]);
        float h2 = gelu_exact((acc[nc][2] - muB) * rsB * sLG[c0]     + sLB[c0]);
        float h3 = gelu_exact((acc[nc][3] - muB) * rsB * sLG[c0 + 1] + sLB[c0 + 1]);
        acc[nc][0] = h0; acc[nc][1] = h1; acc[nc][2] = h2; acc[nc][3] = h3;
#pragma unroll
        for (int j = 0; j < 5; j++) {
            bxA[j] = fmaf(h0, sWn[c0 * 5 + j], fmaf(h1, sWn[(c0 + 1) * 5 + j], bxA[j]));
            bxB[j] = fmaf(h2, sWn[c0 * 5 + j], fmaf(h3, sWn[(c0 + 1) * 5 + j], bxB[j]));
        }
    }
#pragma unroll
    for (int off = 1; off <= 2; off <<= 1)
#pragma unroll
        for (int j = 0; j < 5; j++) {
            bxA[j] += __shfl_xor_sync(0xffffffffu, bxA[j], off);
            bxB[j] += __shfl_xor_sync(0xffffffffu, bxB[j], off);
        }
    if (q == 0) {
        const float* sBn = (const float*)(sm + OFF_BINN);
#pragma unroll
        for (int j = 0; j < 5; j++) {
            g_bx[(base + rA) * 8 + j] = bxA[j] + sBn[j];
            g_bx[(base + rB) * 8 + j] = bxB[j] + sBn[j];
        }
    }

    // repack h into GEMM2 A-fragments (hi only — corr_scale-damped path)
    unsigned fh[8][4];
#pragma unroll
    for (int kc = 0; kc < 8; kc++) {
        fh[kc][0] = pack_b2(__float2bfloat16(acc[2*kc][0]),     __float2bfloat16(acc[2*kc][1]));
        fh[kc][1] = pack_b2(__float2bfloat16(acc[2*kc][2]),     __float2bfloat16(acc[2*kc][3]));
        fh[kc][2] = pack_b2(__float2bfloat16(acc[2*kc + 1][0]), __float2bfloat16(acc[2*kc + 1][1]));
        fh[kc][3] = pack_b2(__float2bfloat16(acc[2*kc + 1][2]), __float2bfloat16(acc[2*kc + 1][3]));
    }

    // ---- GEMM2: acc = h @ Wc1[5:,:]  (single-term bf16), streamed B ----
#pragma unroll
    for (int nc = 0; nc < 16; nc++)
#pragma unroll
        for (int j = 0; j < 4; j++) acc[nc][j] = 0.f;

    for (int kc = 0; kc < 8; kc++) {
        CP_WAIT1();
        __syncthreads();
        if (kc < 6) issue_b2(sm, (kc + 2) % 3, kc + 2, tid);
        CP_COMMIT();

        const char* stg = sm + OFF_BST + (kc % 3) * STG_SZ;
#pragma unroll
        for (int nc = 0; nc < 16; nc++) {
            const char* bp = stg + (nc * 8 + g) * 48 + 4 * q;
            unsigned bh0 = *(const unsigned*)bp;
            unsigned bh1 = *(const unsigned*)(bp + 16);
            MMA16816(acc[nc], fh[kc][0], fh[kc][1], fh[kc][2], fh[kc][3], bh0, bh1);
        }
    }

    // ---- Epilogue B: +bc1 -> g_u ----
    const float* sBC = (const float*)(sm + OFF_BC1);
    const size_t gra = (base + rA) * 128;
    const size_t grb = (base + rB) * 128;
#pragma unroll
    for (int nc = 0; nc < 16; nc++) {
        const int c0 = nc * 8 + 2 * q;
        float bA = sBC[c0], bB = sBC[c0 + 1];
        *(float2*)&g_u[gra + c0] = make_float2(acc[nc][0] + bA, acc[nc][1] + bB);
        *(float2*)&g_u[grb + c0] = make_float2(acc[nc][2] + bA, acc[nc][3] + bB);
    }
}

// ============================================================================
// p2 chunk kernel (proven body, CSTEP=128 steps per launch).
// 128 blocks x 64 threads; state persisted in g_state between launches.
// ============================================================================
__global__ void __launch_bounds__(64)
p2_chunk(const float* __restrict__ Wc1, const float* __restrict__ Wc2,
         const float* __restrict__ bc2, const float* __restrict__ corr_scale,
         const float* __restrict__ raw_aL, const float* __restrict__ raw_aT,
         const float* __restrict__ raw_g,  const float* __restrict__ raw_aR,
         const float* __restrict__ omega,  float* __restrict__ out, int ck)
{
    const int warp = threadIdx.x >> 5, lane = threadIdx.x & 31;
    const int b = blockIdx.x * 2 + warp;

    const float aL = sigmoidf_(raw_aL[0]) * 0.15f + 0.85f;
    const float aT = sigmoidf_(raw_aT[0]) * 0.25f + 0.70f;
    const float gg = sigmoidf_(raw_g[0])  * 0.20f + 0.80f;
    const float aR = sigmoidf_(raw_aR[0]) * 0.40f;
    const float om = omega[0];
    const float gc = gg * cosf(om), gs = gg * sinf(om), ngs = -gs;
    const float cs = corr_scale[0];

    const int c0 = lane * 4;
    float Ws[5][4], Wo[4][5], bb[5];
#pragma unroll
    for (int i = 0; i < 5; i++)
#pragma unroll
        for (int c = 0; c < 4; c++) Ws[i][c] = Wc1[i*128 + c0 + c];
#pragma unroll
    for (int c = 0; c < 4; c++)
#pragma unroll
        for (int k = 0; k < 5; k++) Wo[c][k] = Wc2[(c0 + c)*5 + k];
#pragma unroll
    for (int k = 0; k < 5; k++) bb[k] = bc2[k];

    float s0, s1, s2, s3, s4;
    if (ck == 0) {
        s0 = s1 = s2 = s3 = s4 = 0.f;
    } else {
        s0 = g_state[b*5+0]; s1 = g_state[b*5+1]; s2 = g_state[b*5+2];
        s3 = g_state[b*5+3]; s4 = g_state[b*5+4];
    }

    const float4* up  = (const float4*)(g_u + (size_t)b * NS * 128);
    const float*  bxp = g_bx + (size_t)b * NS * 8;
    const int tbase = ck * CSTEP;

    float4 ub[4], xb[4]; float x4b[4];
#pragma unroll
    for (int j = 0; j < 4; j++) {
        ub[j]  = up[(tbase + j) * 32 + lane];
        xb[j]  = *(const float4*)(bxp + (tbase + j) * 8);
        x4b[j] = bxp[(tbase + j) * 8 + 4];
    }

    for (int t0 = tbase; t0 < tbase + CSTEP; t0 += 4) {
#pragma unroll
        for (int j = 0; j < 4; j++) {
            const int t = t0 + j;
            const float4 u = ub[j];
            const float4 x = xb[j];
            const float  x4 = x4b[j];
            ub[j]  = up[(t + 4) * 32 + lane];
            xb[j]  = *(const float4*)(bxp + (t + 4) * 8);
            x4b[j] = bxp[(t + 4) * 8 + 4];

            float l0 = fmaf(s0, aL, x.x);
            float l1 = fmaf(s1, aT, x.y);
            float l2 = fmaf(s2, gc, fmaf(s3, gs,  x.z));
            float l3 = fmaf(s3, gc, fmaf(s2, ngs, x.w));
            float l4 = fmaf(s4, aR, x4);

            float a0 = u.x, a1 = u.y, a2 = u.z, a3 = u.w;
            a0 = fmaf(l0, Ws[0][0], a0); a1 = fmaf(l0, Ws[0][1], a1);
            a2 = fmaf(l0, Ws[0][2], a2); a3 = fmaf(l0, Ws[0][3], a3);
            a0 = fmaf(l1, Ws[1][0], a0); a1 = fmaf(l1, Ws[1][1], a1);
            a2 = fmaf(l1, Ws[1][2], a2); a3 = fmaf(l1, Ws[1][3], a3);
            a0 = fmaf(l2, Ws[2][0], a0); a1 = fmaf(l2, Ws[2][1], a1);
            a2 = fmaf(l2, Ws[2][2], a2); a3 = fmaf(l2, Ws[2][3], a3);
            a0 = fmaf(l3, Ws[3][0], a0); a1 = fmaf(l3, Ws[3][1], a1);
            a2 = fmaf(l3, Ws[3][2], a2); a3 = fmaf(l3, Ws[3][3], a3);
            a0 = fmaf(l4, Ws[4][0], a0); a1 = fmaf(l4, Ws[4][1], a1);
            a2 = fmaf(l4, Ws[4][2], a2); a3 = fmaf(l4, Ws[4][3], a3);

            float m0 = gelu_fast(a0);
            float m1 = gelu_fast(a1);
            float m2 = gelu_fast(a2);
            float m3 = gelu_fast(a3);

            float p0 = m0*Wo[0][0], p1 = m0*Wo[0][1], p2 = m0*Wo[0][2],
                  p3 = m0*Wo[0][3], p4 = m0*Wo[0][4];
            p0 = fmaf(m1, Wo[1][0], p0); p1 = fmaf(m1, Wo[1][1], p1);
            p2 = fmaf(m1, Wo[1][2], p2); p3 = fmaf(m1, Wo[1][3], p3);
            p4 = fmaf(m1, Wo[1][4], p4);
            p0 = fmaf(m2, Wo[2][0], p0); p1 = fmaf(m2, Wo[2][1], p1);
            p2 = fmaf(m2, Wo[2][2], p2); p3 = fmaf(m2, Wo[2][3], p3);
            p4 = fmaf(m2, Wo[2][4], p4);
            p0 = fmaf(m3, Wo[3][0], p0); p1 = fmaf(m3, Wo[3][1], p1);
            p2 = fmaf(m3, Wo[3][2], p2); p3 = fmaf(m3, Wo[3][3], p3);
            p4 = fmaf(m3, Wo[3][4], p4);

#pragma unroll
            for (int off = 16; off; off >>= 1) {
                p0 += __shfl_xor_sync(0xffffffffu, p0, off);
                p1 += __shfl_xor_sync(0xffffffffu, p1, off);
                p2 += __shfl_xor_sync(0xffffffffu, p2, off);
                p3 += __shfl_xor_sync(0xffffffffu, p3, off);
                p4 += __shfl_xor_sync(0xffffffffu, p4, off);
            }
            s0 = fmaf(cs, tanh_fast(p0 + bb[0]), l0);
            s1 = fmaf(cs, tanh_fast(p1 + bb[1]), l1);
            s2 = fmaf(cs, tanh_fast(p2 + bb[2]), l2);
            s3 = fmaf(cs, tanh_fast(p3 + bb[3]), l3);
            s4 = fmaf(cs, tanh_fast(p4 + bb[4]), l4);
        }
    }

    if (lane == 0) {
        if (ck == NCHUNK - 1) {
            out[b*5+0] = s0; out[b*5+1] = s1; out[b*5+2] = s2;
            out[b*5+3] = s3; out[b*5+4] = s4;
        } else {
            g_state[b*5+0] = s0; g_state[b*5+1] = s1; g_state[b*5+2] = s2;
            g_state[b*5+3] = s3; g_state[b*5+4] = s4;
        }
    }
}

// ============================================================================
extern "C" void kernel_launch(void* const* d_in, const int* in_sizes, int n_in,
                              void* d_out, int out_size)
{
    (void)in_sizes; (void)n_in; (void)out_size;
    const float* x    = (const float*)d_in[0];
    const float* W1   = (const float*)d_in[1];
    const float* b1   = (const float*)d_in[2];
    const float* ln_g = (const float*)d_in[3];
    const float* ln_b = (const float*)d_in[4];
    const float* Winn = (const float*)d_in[5];
    const float* binn = (const float*)d_in[6];
    const float* Wc1  = (const float*)d_in[7];
    const float* bc1  = (const float*)d_in[8];
    const float* Wc2  = (const float*)d_in[9];
    const float* bc2  = (const float*)d_in[10];
    const float* cscl = (const float*)d_in[11];
    const float* raL  = (const float*)d_in[12];
    const float* raT  = (const float*)d_in[13];
    const float* rg   = (const float*)d_in[14];
    const float* raR  = (const float*)d_in[15];
    const float* om   = (const float*)d_in[16];

    static int init_done = 0;
    static cudaStream_t s_side;
    static cudaEvent_t evP1[NCHUNK], evJoin;
    if (!init_done) {
        cudaFuncSetAttribute(p1_mma, cudaFuncAttributeMaxDynamicSharedMemorySize, SMEM_P1);
        cudaStreamCreateWithFlags(&s_side, cudaStreamNonBlocking);
        for (int k = 0; k < NCHUNK; k++)
            cudaEventCreateWithFlags(&evP1[k], cudaEventDisableTiming);
        cudaEventCreateWithFlags(&evJoin, cudaEventDisableTiming);
        init_done = 1;
    }

    // main (capture-origin) stream: prep + producer chunks (256 CTAs each)
    prep_w<<<16, 256>>>(W1, Wc1);
    for (int k = 0; k < NCHUNK; k++) {
        p1_mma<<<NB, 256, SMEM_P1>>>(x, b1, ln_g, ln_b, Winn, binn, bc1, k);
        cudaEventRecord(evP1[k], 0);
    }
    // side stream: consumer chunks, each gated on its producer chunk
    for (int k = 0; k < NCHUNK; k++) {
        cudaStreamWaitEvent(s_side, evP1[k], 0);
        p2_chunk<<<NB / 2, 64, 0, s_side>>>(Wc1, Wc2, bc2, cscl, raL, raT, rg, raR, om,
                                            (float*)d_out, k);
    }
    // join side stream back into the origin stream
    cudaEventRecord(evJoin, s_side);
    cudaStreamWaitEvent(0, evJoin, 0);
}